// round 15
// baseline (speedup 1.0000x reference)
#include <cuda_runtime.h>
#include <cuda_fp16.h>
#include <cstdint>

// Problem dims
#define B_DIM 16384
#define K_DIM 256
#define N_DIM 4096

// Tile config: CTA 128x128, 128 threads (4 warps), 2 CTAs/SM,
// warp grid 2(M) x 2(N), warp tile 64x64.
#define BM 128
#define BN 128
#define KC 64                       // fp16 per K-chunk (one 128B row per chunk)
#define NCHUNK (K_DIM / KC)         // 4
#define NSTAGE 3
#define A_STAGE_BYTES (BM * 128)    // 16 KB
#define B_STAGE_BYTES (BN * 128)    // 16 KB
#define STAGE_BYTES (A_STAGE_BYTES + B_STAGE_BYTES)  // 32 KB
#define SMEM_TOTAL (NSTAGE * STAGE_BYTES)            // 96 KB -> 2 CTAs/SM

// Scratch: fp16(RN) copies. g_wh gathered to [N][K] row-major (k = s*8+cg).
__device__ __half g_xh[B_DIM * K_DIM];   // [B][K]
__device__ __half g_wh[N_DIM * K_DIM];   // [N][K]

// ---------------- helpers ----------------
static __device__ __forceinline__ uint32_t smem_u32(const void* p) {
    uint32_t a;
    asm("{ .reg .u64 t; cvta.to.shared.u64 t, %1; cvt.u32.u64 %0, t; }" : "=r"(a) : "l"(p));
    return a;
}
static __device__ __forceinline__ void ldsm4(uint32_t* r, uint32_t addr) {
    asm volatile("ldmatrix.sync.aligned.m8n8.x4.shared.b16 {%0,%1,%2,%3}, [%4];"
                 : "=r"(r[0]), "=r"(r[1]), "=r"(r[2]), "=r"(r[3]) : "r"(addr));
}
static __device__ __forceinline__ void mma16(float* d, const uint32_t* a, uint32_t b0, uint32_t b1) {
    asm volatile(
        "mma.sync.aligned.m16n8k16.row.col.f32.f16.f16.f32 "
        "{%0,%1,%2,%3}, {%4,%5,%6,%7}, {%8,%9}, {%0,%1,%2,%3};"
        : "+f"(d[0]), "+f"(d[1]), "+f"(d[2]), "+f"(d[3])
        : "r"(a[0]), "r"(a[1]), "r"(a[2]), "r"(a[3]), "r"(b0), "r"(b1));
}
static __device__ __forceinline__ void cp16(uint32_t dst, const __half* src) {
    asm volatile("cp.async.cg.shared.global [%0], [%1], 16;" :: "r"(dst), "l"(src) : "memory");
}

// ---------------- fused repack kernel (fp32 -> fp16 RN, W gather) ----------------
#define XBLKS ((B_DIM * K_DIM / 8) / 256)   // 2048  (8 elems/thread)
#define WBLKS ((N_DIM * K_DIM / 8) / 256)   // 512
__global__ void __launch_bounds__(256) repack_all(const float* __restrict__ x,
                                                  const float* __restrict__ W) {
    int bx = blockIdx.x;
    if (bx < XBLKS) {
        int o = bx * 256 + threadIdx.x;                // 8-float group over x
        const float4* xs = reinterpret_cast<const float4*>(x) + (size_t)o * 2;
        float4 v0 = xs[0], v1 = xs[1];
        __half2* dst = reinterpret_cast<__half2*>(g_xh) + (size_t)o * 4;
        dst[0] = __floats2half2_rn(v0.x, v0.y);
        dst[1] = __floats2half2_rn(v0.z, v0.w);
        dst[2] = __floats2half2_rn(v1.x, v1.y);
        dst[3] = __floats2half2_rn(v1.z, v1.w);
    } else {
        int o = (bx - XBLKS) * 256 + threadIdx.x;      // over N*K/8
        int n = o >> 5, sg = o & 31;                   // slice s = sg, 8 contiguous cg
        const float* src = W + (size_t)sg * (N_DIM * 8) + (size_t)n * 8;
        float4 v0 = *reinterpret_cast<const float4*>(src);
        float4 v1 = *reinterpret_cast<const float4*>(src + 4);
        __half2* dst = reinterpret_cast<__half2*>(g_wh + (size_t)n * K_DIM + sg * 8);
        dst[0] = __floats2half2_rn(v0.x, v0.y);
        dst[1] = __floats2half2_rn(v0.z, v0.w);
        dst[2] = __floats2half2_rn(v1.x, v1.y);
        dst[3] = __floats2half2_rn(v1.z, v1.w);
    }
}

// ---------------- main GEMM kernel ----------------
__global__ void __launch_bounds__(128, 2) slb_gemm(float* __restrict__ out) {
    extern __shared__ char smem[];
    const uint32_t sb = smem_u32(smem);
    const int tid = threadIdx.x;
    const int lane = tid & 31;
    const int wid = tid >> 5;
    const int g = lane >> 2;          // output fragment row group
    const int c = lane & 3;           // output fragment col group
    const int wm = wid & 1;           // warp M index (2)
    const int wn = wid >> 1;          // warp N index (2)

    // m-minor rasterization: consecutive bids sweep M with fixed N tile.
    const int m0 = (int)(blockIdx.x & 127) * BM;   // 128 m-tiles
    const int n0 = (int)(blockIdx.x >> 7) * BN;    // 32 n-tiles

    float acc[4][8][4];
#pragma unroll
    for (int mt = 0; mt < 4; mt++)
#pragma unroll
        for (int nt = 0; nt < 8; nt++)
#pragma unroll
            for (int e = 0; e < 4; e++) acc[mt][nt][e] = 0.0f;

    // cp.async per-thread offsets. A: 1024 16B chunks/stage -> 8/thread; B same.
    uint32_t aoff[8], adst[8], boff[8], bdst[8];
#pragma unroll
    for (int i = 0; i < 8; i++) {
        int id = tid + i * 128;
        int m = id >> 3, w = id & 7;                   // w: 16B chunk (8 fp16)
        aoff[i] = (uint32_t)((m0 + m) * K_DIM + w * 8);
        adst[i] = (uint32_t)(m * 128 + ((w ^ (m & 7)) << 4));
        boff[i] = (uint32_t)((n0 + m) * K_DIM + w * 8);
        bdst[i] = (uint32_t)(A_STAGE_BYTES + m * 128 + ((w ^ (m & 7)) << 4));
    }

#define LOAD_CHUNK(kc, slot)                                                    \
    {                                                                           \
        uint32_t stg_ = sb + (uint32_t)((slot) * STAGE_BYTES);                  \
        uint32_t ko_ = (uint32_t)((kc) * KC);                                   \
        _Pragma("unroll")                                                       \
        for (int i_ = 0; i_ < 8; i_++) {                                        \
            cp16(stg_ + adst[i_], g_xh + aoff[i_] + ko_);                       \
            cp16(stg_ + bdst[i_], g_wh + boff[i_] + ko_);                       \
        }                                                                       \
        asm volatile("cp.async.commit_group;" ::: "memory");                    \
    }

    // Prologue: chunks 0..2 into slots 0..2.
    LOAD_CHUNK(0, 0);
    LOAD_CHUNK(1, 1);
    LOAD_CHUNK(2, 2);

    // ldmatrix per-thread row bases.
    const int q = lane >> 3, tr = lane & 7;
    uint32_t arb[4]; int asw[4];
#pragma unroll
    for (int mt = 0; mt < 4; mt++) {
        int row = wm * 64 + mt * 16 + ((q & 1) << 3) + tr;
        arb[mt] = (uint32_t)(row * 128); asw[mt] = row & 7;
    }
    const int ajb = q >> 1;
    uint32_t brb[4]; int bsw[4];
#pragma unroll
    for (int bg = 0; bg < 4; bg++) {
        int row = wn * 64 + bg * 16 + ((q >> 1) << 3) + tr;
        brb[bg] = (uint32_t)(A_STAGE_BYTES + row * 128); bsw[bg] = row & 7;
    }
    const int bjb = q & 1;

#pragma unroll
    for (int kc = 0; kc < NCHUNK; kc++) {
        // Waits: kc0 needs c0 (<=2 pending), kc1 needs c1 (<=1), kc2 needs c2 (<=1
        // since c3 was committed at kc1), kc3 needs c3 (0).
        if (kc == 0)      asm volatile("cp.async.wait_group 2;" ::: "memory");
        else if (kc == 3) asm volatile("cp.async.wait_group 0;" ::: "memory");
        else              asm volatile("cp.async.wait_group 1;" ::: "memory");
        __syncthreads();
        // Chunk 3 -> slot 0. Issued after the kc=1 barrier, which orders it
        // against all iter-0 reads of slot 0.
        if (kc == 1) LOAD_CHUNK(3, 0);

        const uint32_t st = sb + (uint32_t)((kc % NSTAGE) * STAGE_BYTES);
#pragma unroll
        for (int ks = 0; ks < 4; ks++) {               // 4 x k16 steps per 64-chunk
            uint32_t af[4][4], bf[4][4];
#pragma unroll
            for (int mt = 0; mt < 4; mt++)
                ldsm4(af[mt], st + arb[mt] + (uint32_t)((((2 * ks + ajb) ^ asw[mt])) << 4));
#pragma unroll
            for (int bg = 0; bg < 4; bg++)
                ldsm4(bf[bg], st + brb[bg] + (uint32_t)((((2 * ks + bjb) ^ bsw[bg])) << 4));
#pragma unroll
            for (int mt = 0; mt < 4; mt++)
#pragma unroll
                for (int nt = 0; nt < 8; nt++)
                    mma16(acc[mt][nt], af[mt], bf[nt >> 1][(nt & 1) * 2], bf[nt >> 1][(nt & 1) * 2 + 1]);
        }
    }

    // ---- Epilogue: direct sector-aligned STG.64 from register accumulators ----
    float* op = out + (size_t)(m0 + wm * 64 + g) * N_DIM + (n0 + wn * 64 + 2 * c);
#pragma unroll
    for (int mt = 0; mt < 4; mt++) {
#pragma unroll
        for (int nt = 0; nt < 8; nt++) {
            float2 v0 = make_float2(acc[mt][nt][0], acc[mt][nt][1]);
            float2 v1 = make_float2(acc[mt][nt][2], acc[mt][nt][3]);
            *reinterpret_cast<float2*>(op + (size_t)(mt * 16) * N_DIM + nt * 8) = v0;
            *reinterpret_cast<float2*>(op + (size_t)(mt * 16 + 8) * N_DIM + nt * 8) = v1;
        }
    }
}

// ---------------- launch ----------------
extern "C" void kernel_launch(void* const* d_in, const int* in_sizes, int n_in,
                              void* d_out, int out_size) {
    const float* x = (const float*)d_in[0];
    const float* W = (const float*)d_in[1];
    if (n_in >= 2 && in_sizes[0] == N_DIM * K_DIM && in_sizes[1] == B_DIM * K_DIM) {
        const float* t = x; x = W; W = t;   // defensive order swap
    }
    cudaFuncSetAttribute(slb_gemm, cudaFuncAttributeMaxDynamicSharedMemorySize, SMEM_TOTAL);

    repack_all<<<XBLKS + WBLKS, 256>>>(x, W);
    slb_gemm<<<(B_DIM / BM) * (N_DIM / BN), 128, SMEM_TOTAL>>>((float*)d_out);
}